// round 4
// baseline (speedup 1.0000x reference)
#include <cuda_runtime.h>
#include <cuda_bf16.h>
#include <cstdint>

// SOM layer: coarse bf16 mma.sync GEMM (scores + candidate capture) then
// exact fp32 refinement of candidates -> argmin identical to reference.
// R4: ldmatrix fragment loads, 256x128 CTA tile, 4-stage cp.async pipeline.

#define DDIM 512
#define MAXN 32768
#define MAXM 4096
#define CAND_CAP 64
#define COARSE_THR 1.5f

#define BM 256
#define BN 128
#define BK 32
#define NTHREADS 256       // 8 warps: 4(m) x 2(n), warp tile 64x64
#define STAGES 4
#define A_STAGE_BYTES (BM * 64)            // 16384
#define B_STAGE_BYTES (BN * 64)            // 8192
#define STAGE_BYTES (A_STAGE_BYTES + B_STAGE_BYTES)  // 24576
#define SMEM_BYTES (STAGES * STAGE_BYTES)  // 98304

// ---------------- device global scratch (allocation-free rule) --------------
__device__ float g_p2[MAXM];
__device__ float g_z2[MAXN];
__device__ __align__(128) __nv_bfloat16 g_zbf[MAXN * DDIM];   // 32MB
__device__ __align__(128) __nv_bfloat16 g_pbf[MAXM * DDIM];   // 4MB
__device__ float    g_cval[(size_t)MAXN * CAND_CAP];
__device__ int      g_cidx[(size_t)MAXN * CAND_CAP];
__device__ int      g_ccnt[MAXN];
__device__ unsigned g_best[MAXN];

// ---------------- helpers ----------------------------------------------------
__device__ __forceinline__ uint32_t smem_u32(const void* p) {
    uint32_t a;
    asm("{ .reg .u64 t; cvta.to.shared.u64 t, %1; cvt.u32.u64 %0, t; }"
        : "=r"(a) : "l"(p));
    return a;
}
__device__ __forceinline__ void cp16(uint32_t dst, const void* src) {
    asm volatile("cp.async.cg.shared.global [%0], [%1], 16;" :: "r"(dst), "l"(src));
}
__device__ __forceinline__ void mma16816(float* c, const uint32_t* a,
                                         uint32_t b0, uint32_t b1) {
    asm volatile(
        "mma.sync.aligned.m16n8k16.row.col.f32.bf16.bf16.f32 "
        "{%0,%1,%2,%3}, {%4,%5,%6,%7}, {%8,%9}, {%0,%1,%2,%3};"
        : "+f"(c[0]), "+f"(c[1]), "+f"(c[2]), "+f"(c[3])
        : "r"(a[0]), "r"(a[1]), "r"(a[2]), "r"(a[3]), "r"(b0), "r"(b1));
}
#define LDSM4(r0, r1, r2, r3, addr) \
    asm volatile("ldmatrix.sync.aligned.m8n8.x4.shared.b16 {%0,%1,%2,%3}, [%4];" \
                 : "=r"(r0), "=r"(r1), "=r"(r2), "=r"(r3) : "r"(addr))

// ---------------- init / precompute kernels ----------------------------------
__global__ void zero_kernel(int n) {
    int i = blockIdx.x * blockDim.x + threadIdx.x;
    if (i < n) { g_ccnt[i] = 0; g_best[i] = 0x7F800000u; }
}
__global__ void sq_z_kernel(const float* __restrict__ x, int rows) {
    int warp = (blockIdx.x * blockDim.x + threadIdx.x) >> 5;
    int lane = threadIdx.x & 31;
    if (warp >= rows) return;
    const float4* xr = reinterpret_cast<const float4*>(x) + (size_t)warp * (DDIM / 4);
    float s = 0.f;
#pragma unroll
    for (int i = 0; i < (DDIM / 4) / 32; i++) {
        float4 v = xr[lane + i * 32];
        s += v.x * v.x + v.y * v.y + v.z * v.z + v.w * v.w;
    }
#pragma unroll
    for (int o = 16; o; o >>= 1) s += __shfl_xor_sync(0xffffffffu, s, o);
    if (lane == 0) g_z2[warp] = s;
}
__global__ void sq_p_kernel(const float* __restrict__ x, int rows) {
    int warp = (blockIdx.x * blockDim.x + threadIdx.x) >> 5;
    int lane = threadIdx.x & 31;
    if (warp >= rows) return;
    const float4* xr = reinterpret_cast<const float4*>(x) + (size_t)warp * (DDIM / 4);
    float s = 0.f;
#pragma unroll
    for (int i = 0; i < (DDIM / 4) / 32; i++) {
        float4 v = xr[lane + i * 32];
        s += v.x * v.x + v.y * v.y + v.z * v.z + v.w * v.w;
    }
#pragma unroll
    for (int o = 16; o; o >>= 1) s += __shfl_xor_sync(0xffffffffu, s, o);
    if (lane == 0) g_p2[warp] = s;
}
__device__ __forceinline__ uint32_t packbf(float a, float b) {
    __nv_bfloat162 t = __float22bfloat162_rn(make_float2(a, b));
    return *reinterpret_cast<uint32_t*>(&t);
}
__global__ void cvt_z_kernel(const float* __restrict__ x, int n4) {
    int i = blockIdx.x * blockDim.x + threadIdx.x;
    if (i >= n4) return;
    float4 v = reinterpret_cast<const float4*>(x)[i];
    uint2 u; u.x = packbf(v.x, v.y); u.y = packbf(v.z, v.w);
    reinterpret_cast<uint2*>(g_zbf)[i] = u;
}
__global__ void cvt_p_kernel(const float* __restrict__ x, int n4) {
    int i = blockIdx.x * blockDim.x + threadIdx.x;
    if (i >= n4) return;
    float4 v = reinterpret_cast<const float4*>(x)[i];
    uint2 u; u.x = packbf(v.x, v.y); u.y = packbf(v.z, v.w);
    reinterpret_cast<uint2*>(g_pbf)[i] = u;
}

// ---------------- main coarse GEMM + candidate capture ----------------------
// smem layout per stage: A (256 rows x 64B, XOR-swizzled) then B (128 x 64B).
// swizzled chunk address: row*64 + ((chunk ^ ((row>>1)&3)) * 16)
__global__ __launch_bounds__(NTHREADS, 1)
void som_mma_kernel() {
    extern __shared__ __align__(128) unsigned char smem[];
    __shared__ unsigned srow[BM];

    const int tid = threadIdx.x;
    const int wid = tid >> 5;
    const int lane = tid & 31;
    const int wm = wid >> 1;          // 0..3
    const int wn = wid & 1;           // 0..1
    const int m8 = lane >> 3;         // ldmatrix matrix id 0..3
    const int r8 = lane & 7;
    const int crow = lane >> 2;       // mma C row within 8
    const int qc = lane & 3;

    const int rowBase = blockIdx.x * BM;
    const int colBase = blockIdx.y * BN;

    const __nv_bfloat16* gA = g_zbf + (size_t)rowBase * DDIM;
    const __nv_bfloat16* gB = g_pbf + (size_t)colBase * DDIM;

    const uint32_t sbase = smem_u32(smem);

    if (tid < BM) srow[tid] = 0xFFFFFFFFu;

    // per-lane ldmatrix offsets (stage-relative)
    uint32_t aOff[2][4], bOff[2][4];
    {
        int rowW = wm * 64 + (m8 & 1) * 8 + r8;            // A row, mi-invariant swizzle
        int sxa = (rowW >> 1) & 3;
#pragma unroll
        for (int kf = 0; kf < 2; kf++)
#pragma unroll
            for (int mi = 0; mi < 4; mi++)
                aOff[kf][mi] = (uint32_t)((rowW + mi * 16) * 64 +
                               (((kf * 2 + (m8 >> 1)) ^ sxa) << 4));
        int nW = wn * 64 + (m8 >> 1) * 8 + r8;             // B row base, p-invariant swizzle
        int sxb = (nW >> 1) & 3;
#pragma unroll
        for (int kf = 0; kf < 2; kf++)
#pragma unroll
            for (int p = 0; p < 4; p++)
                bOff[kf][p] = (uint32_t)(A_STAGE_BYTES + (nW + p * 16) * 64 +
                              (((kf * 2 + (m8 & 1)) ^ sxb) << 4));
    }

    float acc[4][8][4];
#pragma unroll
    for (int mi = 0; mi < 4; mi++)
#pragma unroll
        for (int ni = 0; ni < 8; ni++)
#pragma unroll
            for (int c = 0; c < 4; c++) acc[mi][ni][c] = 0.f;

    const int KT = DDIM / BK;  // 16

    auto loadStage = [&](int st, int kt) {
        const uint32_t base = sbase + st * STAGE_BYTES;
        // A: 1024 16B chunks
#pragma unroll
        for (int i = 0; i < 4; i++) {
            int id = tid + i * NTHREADS;
            int r = id >> 2, c = id & 3;
            cp16(base + r * 64 + (((c ^ ((r >> 1) & 3))) << 4),
                 gA + (size_t)r * DDIM + kt * BK + c * 8);
        }
        // B: 512 16B chunks
#pragma unroll
        for (int i = 0; i < 2; i++) {
            int id = tid + i * NTHREADS;
            int r = id >> 2, c = id & 3;
            cp16(base + A_STAGE_BYTES + r * 64 + (((c ^ ((r >> 1) & 3))) << 4),
                 gB + (size_t)r * DDIM + kt * BK + c * 8);
        }
        asm volatile("cp.async.commit_group;");
    };

    loadStage(0, 0);
    loadStage(1, 1);
    loadStage(2, 2);

    for (int kt = 0; kt < KT; kt++) {
        asm volatile("cp.async.wait_group 2;");
        __syncthreads();
        if (kt + 3 < KT) loadStage((kt + 3) & 3, kt + 3);

        const uint32_t stg = sbase + (kt & 3) * STAGE_BYTES;
#pragma unroll
        for (int kf = 0; kf < 2; kf++) {
            uint32_t a[4][4];
#pragma unroll
            for (int mi = 0; mi < 4; mi++)
                LDSM4(a[mi][0], a[mi][1], a[mi][2], a[mi][3], stg + aOff[kf][mi]);
#pragma unroll
            for (int p = 0; p < 4; p++) {
                uint32_t b0, b1, b2, b3;
                LDSM4(b0, b1, b2, b3, stg + bOff[kf][p]);
#pragma unroll
                for (int mi = 0; mi < 4; mi++) {
                    mma16816(acc[mi][2 * p],     a[mi], b0, b1);
                    mma16816(acc[mi][2 * p + 1], a[mi], b2, b3);
                }
            }
        }
        __syncthreads();
    }

    // ---- epilogue: d = z2 - 2*dot + p2, per-row min, candidate append -------
#pragma unroll
    for (int mi = 0; mi < 4; mi++) {
#pragma unroll
        for (int h = 0; h < 2; h++) {
            int lrow = wm * 64 + mi * 16 + crow + h * 8;
            float z2v = g_z2[rowBase + lrow];
            float tmin = 3.4e38f;
#pragma unroll
            for (int ni = 0; ni < 8; ni++) {
                int gcol = colBase + wn * 64 + ni * 8 + 2 * qc;
                float d0 = (z2v - 2.0f * acc[mi][ni][2 * h])     + __ldg(&g_p2[gcol]);
                float d1 = (z2v - 2.0f * acc[mi][ni][2 * h + 1]) + __ldg(&g_p2[gcol + 1]);
                acc[mi][ni][2 * h] = d0;
                acc[mi][ni][2 * h + 1] = d1;
                tmin = fminf(tmin, fminf(d0, d1));
            }
            atomicMin(&srow[lrow], __float_as_uint(tmin));
        }
    }
    __syncthreads();

    if (tid < BM) atomicMin(&g_best[rowBase + tid], srow[tid]);

#pragma unroll
    for (int mi = 0; mi < 4; mi++) {
#pragma unroll
        for (int h = 0; h < 2; h++) {
            int lrow = wm * 64 + mi * 16 + crow + h * 8;
            int grow = rowBase + lrow;
            float gb = fminf(__uint_as_float(g_best[grow]),
                             __uint_as_float(srow[lrow]));
            float thr = gb + COARSE_THR;
#pragma unroll
            for (int ni = 0; ni < 8; ni++) {
                int gcol = colBase + wn * 64 + ni * 8 + 2 * qc;
#pragma unroll
                for (int e = 0; e < 2; e++) {
                    float d = acc[mi][ni][2 * h + e];
                    if (d < thr) {
                        int slot = atomicAdd(&g_ccnt[grow], 1);
                        if (slot < CAND_CAP) {
                            g_cval[(size_t)grow * CAND_CAP + slot] = d;
                            g_cidx[(size_t)grow * CAND_CAP + slot] = gcol + e;
                        }
                    }
                }
            }
        }
    }
}

// ---------------- exact refinement + output ---------------------------------
__global__ void refine_kernel(const float* __restrict__ z,
                              const float* __restrict__ proto, int Mtot,
                              float* __restrict__ outW,
                              float* __restrict__ outIdxF,
                              int* __restrict__ outIdxI) {
    int warp = (blockIdx.x * blockDim.x + threadIdx.x) >> 5;
    int lane = threadIdx.x & 31;
    const int row = warp;
    const float z2 = g_z2[row];

    float4 zr[4];
#pragma unroll
    for (int i = 0; i < 4; i++)
        zr[i] = reinterpret_cast<const float4*>(z + (size_t)row * DDIM)[i * 32 + lane];

    int cnt = g_ccnt[row];
    float bestD = 3.4e38f;
    int bestI = 0;

    if (cnt <= CAND_CAP) {
        for (int k = 0; k < cnt; k++) {
            int c = g_cidx[(size_t)row * CAND_CAP + k];
            const float4* pr = reinterpret_cast<const float4*>(proto + (size_t)c * DDIM);
            float dot = 0.f;
#pragma unroll
            for (int i = 0; i < 4; i++) {
                float4 pv = pr[i * 32 + lane];
                dot += zr[i].x * pv.x + zr[i].y * pv.y + zr[i].z * pv.z + zr[i].w * pv.w;
            }
#pragma unroll
            for (int o = 16; o; o >>= 1) dot += __shfl_xor_sync(0xffffffffu, dot, o);
            float d = (z2 - 2.0f * dot) + __ldg(&g_p2[c]);
            if (d < bestD || (d == bestD && c < bestI)) { bestD = d; bestI = c; }
        }
    } else {
        for (int c = 0; c < Mtot; c++) {
            const float4* pr = reinterpret_cast<const float4*>(proto + (size_t)c * DDIM);
            float dot = 0.f;
#pragma unroll
            for (int i = 0; i < 4; i++) {
                float4 pv = pr[i * 32 + lane];
                dot += zr[i].x * pv.x + zr[i].y * pv.y + zr[i].z * pv.z + zr[i].w * pv.w;
            }
#pragma unroll
            for (int o = 16; o; o >>= 1) dot += __shfl_xor_sync(0xffffffffu, dot, o);
            float d = (z2 - 2.0f * dot) + __ldg(&g_p2[c]);
            if (d < bestD) { bestD = d; bestI = c; }
        }
    }

    if (lane == 0) {
        if (outIdxF) outIdxF[row] = (float)bestI;
        if (outIdxI) outIdxI[row] = bestI;
    }
    if (outW) {
        const float4* pr = reinterpret_cast<const float4*>(proto + (size_t)bestI * DDIM);
        float4* ow = reinterpret_cast<float4*>(outW + (size_t)row * DDIM);
#pragma unroll
        for (int i = 0; i < 4; i++) ow[i * 32 + lane] = pr[i * 32 + lane];
    }
}

// ---------------------------------------------------------------------------
extern "C" void kernel_launch(void* const* d_in, const int* in_sizes, int n_in,
                              void* d_out, int out_size) {
    const float* z = (const float*)d_in[0];
    const float* p = (const float*)d_in[1];
    int N = in_sizes[0] / DDIM;
    int M = in_sizes[1] / DDIM;

    zero_kernel<<<(N + 255) / 256, 256>>>(N);
    sq_p_kernel<<<(M * 32 + 255) / 256, 256>>>(p, M);
    sq_z_kernel<<<(N * 32 + 255) / 256, 256>>>(z, N);
    cvt_p_kernel<<<(M * (DDIM / 4) + 255) / 256, 256>>>(p, M * (DDIM / 4));
    cvt_z_kernel<<<(N * (DDIM / 4) + 255) / 256, 256>>>(z, N * (DDIM / 4));

    cudaFuncSetAttribute(som_mma_kernel,
                         cudaFuncAttributeMaxDynamicSharedMemorySize, SMEM_BYTES);
    dim3 grid(N / BM, M / BN);   // x = row tiles (fast), y = col tiles
    som_mma_kernel<<<grid, NTHREADS, SMEM_BYTES>>>();

    float* outW = nullptr;
    float* outIdxF = nullptr;
    int* outIdxI = nullptr;
    long long nd = (long long)N * DDIM;
    if ((long long)out_size >= nd) {
        outW = (float*)d_out;
        if ((long long)out_size >= nd + N) outIdxF = (float*)d_out + nd;
    } else if (out_size == N) {
        outIdxI = (int*)d_out;
    }

    refine_kernel<<<(N * 32) / 256, 256>>>(z, p, M, outW, outIdxF, outIdxI);
}